// round 2
// baseline (speedup 1.0000x reference)
#include <cuda_runtime.h>

#define N_MOLS  32768
#define N_ATOMS 4194304
#define THREADS 256
#define APT     8                               // atoms per thread
#define N_THREADS_TOTAL (N_ATOMS / APT)         // 524288
#define N_BLOCKS (N_THREADS_TOTAL / THREADS)    // 2048

__global__ void zero_energy_kernel(float* __restrict__ energy) {
    int i = blockIdx.x * blockDim.x + threadIdx.x;
    if (i < N_MOLS) energy[i] = 0.0f;
}

__device__ __forceinline__ float tanh_approx(float x) {
    float y;
    asm("tanh.approx.f32 %0, %1;" : "=f"(y) : "f"(x));
    return y;
}

__global__ __launch_bounds__(THREADS) void sumpool_kernel(
    const float4* __restrict__ xyz4,     // N_ATOMS*3 floats as float4
    const int4*   __restrict__ ids4,     // N_ATOMS ints as int4
    const float*  __restrict__ w,        // 3 floats
    float*        __restrict__ energy,   // N_MOLS
    float4*       __restrict__ grad4)    // N_ATOMS*3 floats as float4
{
    const int tid  = blockIdx.x * blockDim.x + threadIdx.x;  // 0..524287
    const int lane = threadIdx.x & 31;

    const float w0 = __ldg(w + 0);
    const float w1 = __ldg(w + 1);
    const float w2 = __ldg(w + 2);

    // Front-batched loads: 8 atoms = 6 float4 (xyz) + 2 int4 (ids), MLP=8
    float4 x[6];
    #pragma unroll
    for (int j = 0; j < 6; j++) x[j] = __ldcs(&xyz4[(long)tid * 6 + j]);
    int4 idv[2];
    idv[0] = __ldcs(&ids4[tid * 2 + 0]);
    idv[1] = __ldcs(&ids4[tid * 2 + 1]);

    const float* f  = (const float*)x;
    const int*   id = (const int*)idv;

    float t[APT], g[APT];
    #pragma unroll
    for (int k = 0; k < APT; k++) {
        const float u = f[3*k] * w0 + f[3*k+1] * w1 + f[3*k+2] * w2;
        t[k] = tanh_approx(u);
        g[k] = 1.0f - t[k] * t[k];
    }

    // gradient output: same packing as xyz
    float o[24];
    #pragma unroll
    for (int k = 0; k < APT; k++) {
        o[3*k]   = g[k] * w0;
        o[3*k+1] = g[k] * w1;
        o[3*k+2] = g[k] * w2;
    }
    const float4* o4 = (const float4*)o;
    #pragma unroll
    for (int j = 0; j < 6; j++) __stcs(&grad4[(long)tid * 6 + j], o4[j]);

    // ---- segment sum of t[0..7] over sorted ids ----
    int   cur = id[0];
    float s   = t[0];
    #pragma unroll
    for (int k = 1; k < APT; k++) {
        if (id[k] == cur) { s += t[k]; }
        else { atomicAdd(&energy[cur], s); cur = id[k]; s = t[k]; }
    }

    // warp-level segmented reduction on tail runs (ids sorted)
    #pragma unroll
    for (int off = 1; off < 32; off <<= 1) {
        const float v   = __shfl_down_sync(0xffffffffu, s,   off);
        const int   oid = __shfl_down_sync(0xffffffffu, cur, off);
        if (lane + off < 32 && oid == cur) s += v;
    }
    const int prev = __shfl_up_sync(0xffffffffu, cur, 1);
    if (lane == 0 || prev != cur) {
        atomicAdd(&energy[cur], s);
    }
}

extern "C" void kernel_launch(void* const* d_in, const int* in_sizes, int n_in,
                              void* d_out, int out_size) {
    const float4* xyz4 = (const float4*)d_in[0];
    const int4*   ids4 = (const int4*)d_in[1];
    const float*  w    = (const float*)d_in[2];

    float* energy = (float*)d_out;                      // [N_MOLS]
    float4* grad4 = (float4*)((float*)d_out + N_MOLS);  // [N_ATOMS*3]

    zero_energy_kernel<<<(N_MOLS + 255) / 256, 256>>>(energy);
    sumpool_kernel<<<N_BLOCKS, THREADS>>>(xyz4, ids4, w, energy, grad4);
}